// round 16
// baseline (speedup 1.0000x reference)
#include <cuda_runtime.h>
#include <cuda_fp16.h>
#include <math.h>
#include <cstdint>

#define Bdim 128
#define Tdim 24
#define Edim 512
#define Hdim 512
#define Rdim 512
#define NTG 400
#define Vdim 20000
#define NPAD 20224          // 158*128
#define TBdim (Tdim*Bdim)   // 3072
#define RC 128              // persistent recurrence CTAs

// ---------------- scratch (device globals; no allocation allowed) ----------
__device__ float g_t2[4*Bdim*Rdim];
__device__ float g_t5[4*Bdim*Rdim];
__device__ float g_gx[4L*TBdim*Hdim];
__device__ float g_gh[4*Bdim*Hdim];
__device__ float g_c[Bdim*Hdim];
__device__ unsigned g_sync;
__device__ unsigned g_sync2;
// chunk-major swizzled fp16 layouts (hi-only): [.. chunk ..][rows][64]
__device__ __half g_x2C[8L*TBdim*64];           // xs hi
__device__ __half g_t1C[4L*8*TBdim*64];         // t1 hi per gate
__device__ __half g_hC[8L*Bdim*64];             // h hi
__device__ __half g_t6C[4L*8*Bdim*64];          // t6 hi per gate
__device__ __half g_WaC[4L*8*Rdim*64];          // Wa^T hi per gate
__device__ __half g_WcC[4L*8*Rdim*64];          // Wc^T hi per gate
__device__ __half g_hsC[8L*TBdim*64];           // hs hi (out GEMM A)
__device__ __half g_WoC[8L*NPAD*64];            // Wout^T hi (out GEMM B)

__device__ __forceinline__ uint32_t smem_u32(const void* p) {
    uint32_t a;
    asm("{ .reg .u64 t; cvta.to.shared.u64 t, %1; cvt.u32.u64 %0, t; }" : "=r"(a) : "l"(p));
    return a;
}

__device__ __forceinline__ void ldm_x4(uint32_t* r, uint32_t addr)
{
    asm volatile("ldmatrix.sync.aligned.m8n8.x4.shared.b16 {%0,%1,%2,%3}, [%4];"
        : "=r"(r[0]), "=r"(r[1]), "=r"(r[2]), "=r"(r[3]) : "r"(addr));
}

__device__ __forceinline__ void mma16816(float* c, const uint32_t* a, const uint32_t* b)
{
    asm volatile("mma.sync.aligned.m16n8k16.row.col.f32.f16.f16.f32 "
        "{%0,%1,%2,%3}, {%4,%5,%6,%7}, {%8,%9}, {%0,%1,%2,%3};"
        : "+f"(c[0]), "+f"(c[1]), "+f"(c[2]), "+f"(c[3])
        : "r"(a[0]), "r"(a[1]), "r"(a[2]), "r"(a[3]), "r"(b[0]), "r"(b[1]));
}

#define MBARRIER_INIT(mbar, cnt) \
    asm volatile("mbarrier.init.shared.b64 [%0], %1;" :: "r"((uint32_t)(mbar)), "r"((uint32_t)(cnt)) : "memory")
#define MBARRIER_ARRIVE(mbar) \
    asm volatile("mbarrier.arrive.shared.b64 _, [%0];" :: "r"((uint32_t)(mbar)) : "memory")
#define MBARRIER_WAIT_PARITY(mbar, par) do { \
    uint32_t _m = (uint32_t)(mbar), _p = (uint32_t)(par), _d; \
    asm volatile("{\n\t.reg .pred p;\n\t" \
        "mbarrier.try_wait.parity.acquire.cta.shared::cta.b64 p, [%1], %2;\n\t" \
        "selp.b32 %0, 1, 0, p;\n\t}" : "=r"(_d) : "r"(_m), "r"(_p) : "memory"); \
    if (!_d) { \
        asm volatile("{\n\t.reg .pred P1;\n\t" \
            "WL_%=:\n\t" \
            "mbarrier.try_wait.parity.acquire.cta.shared::cta.b64 P1, [%0], %1, 0x989680;\n\t" \
            "@P1 bra.uni WD_%=;\n\t" \
            "bra.uni WL_%=;\n\t" \
            "WD_%=:\n\t}" :: "r"(_m), "r"(_p) : "memory"); \
    } \
} while (0)
#define BULK_CP(dst, src, bytes, bar) \
    asm volatile("cp.async.bulk.shared::cluster.global.mbarrier::complete_tx::bytes " \
        "[%0], [%1], %2, [%3];" :: "r"(dst), "l"(src), "r"((uint32_t)(bytes)), "r"(bar) : "memory")
#define BAR_EXPECT(bar, bytes) \
    asm volatile("mbarrier.arrive.expect_tx.shared.b64 _, [%0], %1;" \
        :: "r"(bar), "r"((uint32_t)(bytes)) : "memory")

// ================= unified hi-only MMA GEMM (out / t1 / gx) =================
// 256 threads, 8 warps (2 x 4), CTA tile 128x128, warp tile 64x32. 2 CTAs/SM.
#define MM_STAGE 32768
#define MM_SMEM  (3*MM_STAGE + 64)

__device__ __forceinline__ void mm_issue(uint32_t sb, uint32_t mb, int k,
                                         const __half* Ac, const __half* Bc,
                                         int mtile, int ntile, int bRows)
{
    int slot = k % 3;
    uint32_t dst = sb + slot*MM_STAGE;
    uint32_t bar = mb + slot*8;
    BAR_EXPECT(bar, 32768u);
    BULK_CP(dst, Ac + ((long)k*TBdim + mtile*128)*64, 16384u, bar);
    BULK_CP(dst + 16384, Bc + ((long)k*bRows + ntile*128)*64, 16384u, bar);
}

template<int MODE>
__global__ void __launch_bounds__(256, 2) mm_k(
    const __half* __restrict__ A, const __half* __restrict__ B,
    float* __restrict__ Cf, __half* __restrict__ Cb,
    const float* __restrict__ X, long aS, long bS, int bRows, int mOff)
{
    extern __shared__ char smem[];
    const uint32_t sb = smem_u32(smem);
    const uint32_t mb = sb + 3*MM_STAGE;
    const int tid = threadIdx.x, wid = tid >> 5, lane = tid & 31;
    const int wm = wid & 1, wn = wid >> 1;
    const int mtile = blockIdx.x + mOff, ntile = blockIdx.y, z = blockIdx.z;

    const __half* Az = A + (long)z*aS;
    const __half* Bz = B + (long)z*bS;

    if (tid == 0) {
#pragma unroll
        for (int s = 0; s < 3; s++) {
            MBARRIER_INIT(mb + s*8, 1);
            MBARRIER_INIT(mb + 24 + s*8, 256);
        }
    }
    __syncthreads();
    if (tid == 0) {
        mm_issue(sb, mb, 0, Az, Bz, mtile, ntile, bRows);
        mm_issue(sb, mb, 1, Az, Bz, mtile, ntile, bRows);
        mm_issue(sb, mb, 2, Az, Bz, mtile, ntile, bRows);
    }

    float acc[4][4][4];
#pragma unroll
    for (int i = 0; i < 4; i++)
#pragma unroll
        for (int j = 0; j < 4; j++)
#pragma unroll
            for (int q = 0; q < 4; q++) acc[i][j][q] = 0.f;

    for (int k = 0; k < 8; k++) {
        int slot = k % 3;
        MBARRIER_WAIT_PARITY(mb + slot*8, (k/3) & 1);

        uint32_t sA = sb + slot*MM_STAGE;
        uint32_t sB = sA + 16384;
#pragma unroll
        for (int ks = 0; ks < 4; ks++) {
            uint32_t b[4][2];
#pragma unroll
            for (int np = 0; np < 2; np++) {
                uint32_t n = wn*32 + np*16 + (lane & 7) + ((lane >> 4) & 1)*8;
                uint32_t q = ks*2 + ((lane >> 3) & 1);
                uint32_t r[4];
                ldm_x4(r, sB + n*128 + (q ^ (n & 7))*16);
                b[np*2][0] = r[0];   b[np*2][1] = r[1];
                b[np*2+1][0] = r[2]; b[np*2+1][1] = r[3];
            }
            uint32_t a[4][4];
#pragma unroll
            for (int mi = 0; mi < 4; mi++) {
                uint32_t m = wm*64 + mi*16 + (lane & 15);
                uint32_t q = ks*2 + (lane >> 4);
                ldm_x4(a[mi], sA + m*128 + (q ^ (m & 7))*16);
            }
#pragma unroll
            for (int mi = 0; mi < 4; mi++)
#pragma unroll
                for (int ni = 0; ni < 4; ni++)
                    mma16816(acc[mi][ni], a[mi], b[ni]);
        }
        MBARRIER_ARRIVE(mb + 24 + slot*8);
        if (tid == 0 && k < 5) {
            MBARRIER_WAIT_PARITY(mb + 24 + slot*8, (k/3) & 1);
            mm_issue(sb, mb, k + 3, Az, Bz, mtile, ntile, bRows);
        }
    }

#pragma unroll
    for (int mi = 0; mi < 4; mi++) {
#pragma unroll
        for (int ni = 0; ni < 4; ni++) {
            int n = ntile*128 + wn*32 + ni*8 + (lane & 3)*2;
            int gr0 = mtile*128 + wm*64 + mi*16 + (lane >> 2);
            int gr1 = gr0 + 8;
            if (MODE == 0) {
                if (n < Vdim) {
                    float2 bv = *(const float2*)(X + n);
                    long o0 = ((long)(gr0 & 127)*Tdim + (gr0 >> 7))*Vdim + n;
                    long o1 = ((long)(gr1 & 127)*Tdim + (gr1 >> 7))*Vdim + n;
                    *(float2*)(Cf + o0) = make_float2(acc[mi][ni][0] + bv.x, acc[mi][ni][1] + bv.y);
                    *(float2*)(Cf + o1) = make_float2(acc[mi][ni][2] + bv.x, acc[mi][ni][3] + bv.y);
                }
            } else if (MODE == 1) {
                const float* Xg = X + (long)z*Bdim*Rdim;
                __half* Cz = Cb + (long)z*(8L*TBdim*64);
                int chunk = n >> 6, q = (n & 63) >> 3;
                __half2 h0 = __floats2half2_rn(acc[mi][ni][0]*Xg[(gr0 & 127)*512 + n],
                                               acc[mi][ni][1]*Xg[(gr0 & 127)*512 + n + 1]);
                __half2 h1 = __floats2half2_rn(acc[mi][ni][2]*Xg[(gr1 & 127)*512 + n],
                                               acc[mi][ni][3]*Xg[(gr1 & 127)*512 + n + 1]);
                *(__half2*)(Cz + ((long)chunk*TBdim + gr0)*64 + (q ^ (gr0 & 7))*8 + (n & 7)) = h0;
                *(__half2*)(Cz + ((long)chunk*TBdim + gr1)*64 + (q ^ (gr1 & 7))*8 + (n & 7)) = h1;
            } else {
                const float* Xg = X + z*512;
                float* Cz = Cf + (long)z*TBdim*512;
                float2 bv = make_float2(Xg[n], Xg[n + 1]);
                *(float2*)(Cz + (long)gr0*512 + n) = make_float2(acc[mi][ni][0] + bv.x, acc[mi][ni][1] + bv.y);
                *(float2*)(Cz + (long)gr1*512 + n) = make_float2(acc[mi][ni][2] + bv.x, acc[mi][ni][3] + bv.y);
            }
        }
    }
}

// ---------------- conversions ------------------------------------------------
__global__ void __launch_bounds__(256) k_convWC(const float* __restrict__ Wa,
                                                const float* __restrict__ Wc)
{
    __shared__ float t[64][33];
    const int tid = threadIdx.x;
    const int z = blockIdx.z;
    const int g = z & 3;
    const float* W = (z < 4) ? Wa : Wc;
    __half* Bp = (z < 4) ? g_WaC : g_WcC;
    const int n0 = blockIdx.x*32;
    const int k0 = blockIdx.y*64;
    for (int e = tid; e < 64*32; e += 256) {
        int kk = e >> 5, nn = e & 31;
        t[kk][nn] = W[((long)g*512 + k0 + kk)*512 + n0 + nn];
    }
    __syncthreads();
    int nn = tid >> 3, q = tid & 7;
    int n = n0 + nn;
    __half h[8];
#pragma unroll
    for (int i = 0; i < 8; i++) h[i] = __float2half_rn(t[q*8 + i][nn]);
    int qs = q ^ (n & 7);
    *(uint4*)(Bp + (((long)g*8 + blockIdx.y)*512 + n)*64 + qs*8) = *(uint4*)h;
}

__global__ void __launch_bounds__(256) k_convB(const float* __restrict__ Wout)
{
    __shared__ float t[64][132];
    const int tid = threadIdx.x;
    const int n0 = blockIdx.x*128;
    const int k0 = blockIdx.y*64;
#pragma unroll
    for (int i = 0; i < 8; i++) {
        int e = tid + i*256;
        int kk = e >> 5;
        int nf = (e & 31)*4;
        int n = n0 + nf;
        float4 v;
        if (n + 3 < Vdim) {
            v = *(const float4*)(Wout + (long)(k0 + kk)*Vdim + n);
        } else {
            v.x = (n + 0 < Vdim) ? Wout[(long)(k0+kk)*Vdim + n + 0] : 0.f;
            v.y = (n + 1 < Vdim) ? Wout[(long)(k0+kk)*Vdim + n + 1] : 0.f;
            v.z = (n + 2 < Vdim) ? Wout[(long)(k0+kk)*Vdim + n + 2] : 0.f;
            v.w = (n + 3 < Vdim) ? Wout[(long)(k0+kk)*Vdim + n + 3] : 0.f;
        }
        *(float4*)&t[kk][nf] = v;
    }
    __syncthreads();
    int nn = tid >> 1;
    int n = n0 + nn;
    int hs = (tid & 1)*4;
#pragma unroll
    for (int j = 0; j < 4; j++) {
        int q = hs + j;
        __half h[8];
#pragma unroll
        for (int i = 0; i < 8; i++) h[i] = __float2half_rn(t[q*8 + i][nn]);
        int qs = q ^ (n & 7);
        *(uint4*)(g_WoC + ((long)blockIdx.y*NPAD + n)*64 + qs*8) = *(uint4*)h;
    }
}

// ---------------- embedding gather -> x2C hi-only ----------------------------
__global__ void k_gather(const int* __restrict__ caps, const float* __restrict__ emb)
{
    const int b = blockIdx.x, t = blockIdx.y;
    float4 v = make_float4(0.f, 0.f, 0.f, 0.f);
    if (t > 0) {
        int tok = caps[b*Tdim + (t-1)];
        v = ((const float4*)(emb + (long)tok*Edim))[threadIdx.x];
    }
    __half hv[4];
    hv[0] = __float2half_rn(v.x); hv[1] = __float2half_rn(v.y);
    hv[2] = __float2half_rn(v.z); hv[3] = __float2half_rn(v.w);
    int col = threadIdx.x*4;
    int row = t*Bdim + b;
    int chunk = col >> 6, q = (col & 63) >> 3;
    *(uint2*)(g_x2C + ((long)chunk*TBdim + row)*64 + (q ^ (row & 7))*8 + (col & 7)) = *(uint2*)hv;
}

__global__ void k_init(const float* __restrict__ h0, const float* __restrict__ c0)
{
    int i = blockIdx.x*blockDim.x + threadIdx.x;
    int b = i >> 9, col = i & 511;
    int chunk = col >> 6, q = (col & 63) >> 3;
    g_hC[((long)chunk*Bdim + b)*64 + (q ^ (b & 7))*8 + (col & 7)] = __float2half_rn(h0[i]);
    g_c[i] = c0[i];
    if (i == 0) { g_sync = 0; g_sync2 = 0; }
}

// ---------------- fp32 tiled SGEMM (t2 and t5 in one launch) -----------------
template<int BM,int BN,int BK,int TM,int TN>
__global__ void gemm_k(const float* __restrict__ A,
                       const float* __restrict__ Bm, const float* __restrict__ Bm2,
                       float* __restrict__ C, float* __restrict__ C2,
                       int M, int N, int K, long sB, long sC)
{
    constexpr int THREADS = (BM/TM)*(BN/TN);
    __shared__ float As[BK][BM];
    __shared__ float Bs[BK][BN];
    const int z = blockIdx.z;
    const int g = z & 3;
    const float* Bg = (z < 4 ? Bm : Bm2) + (long)g*sB;
    float* Cg = (z < 4 ? C : C2) + (long)g*sC;
    const int m0 = blockIdx.y*BM;
    const int n0 = blockIdx.x*BN;
    const int tid = threadIdx.x;
    constexpr int AK4 = BK/4;
    const int aRow = tid / AK4, aCol = (tid % AK4)*4;
    constexpr int AROWS = THREADS/AK4;
    constexpr int BN4 = BN/4;
    const int bRow = tid / BN4, bCol = (tid % BN4)*4;
    constexpr int BROWS = THREADS/BN4;
    const int tr = (tid/(BN/TN))*TM, tc = (tid%(BN/TN))*TN;

    float acc[TM][TN];
#pragma unroll
    for (int i = 0; i < TM; i++)
#pragma unroll
        for (int j = 0; j < TN; j++) acc[i][j] = 0.f;

    for (int k0 = 0; k0 < K; k0 += BK) {
#pragma unroll
        for (int i = 0; i < BM; i += AROWS) {
            float4 v = *(const float4*)(A + (long)(m0 + aRow + i)*K + (k0 + aCol));
            As[aCol+0][aRow+i] = v.x; As[aCol+1][aRow+i] = v.y;
            As[aCol+2][aRow+i] = v.z; As[aCol+3][aRow+i] = v.w;
        }
#pragma unroll
        for (int i = 0; i < BK; i += BROWS) {
            float4 v = *(const float4*)(Bg + (long)(k0 + bRow + i)*N + (n0 + bCol));
            *(float4*)&Bs[bRow+i][bCol] = v;
        }
        __syncthreads();
#pragma unroll
        for (int kk = 0; kk < BK; kk++) {
            float rm[TM], rn[TN];
#pragma unroll
            for (int i = 0; i < TM; i++) rm[i] = As[kk][tr+i];
#pragma unroll
            for (int j = 0; j < TN; j++) rn[j] = Bs[kk][tc+j];
#pragma unroll
            for (int i = 0; i < TM; i++)
#pragma unroll
                for (int j = 0; j < TN; j++)
                    acc[i][j] = fmaf(rm[i], rn[j], acc[i][j]);
        }
        __syncthreads();
    }
#pragma unroll
    for (int i = 0; i < TM; i++)
#pragma unroll
        for (int j = 0; j < TN; j++)
            Cg[(long)(m0 + tr + i)*N + n0 + tc + j] = acc[i][j];
}

// ---------------- persistent tensor-core recurrence (hi A, hi W) -------------
#define RW_STRIDE 1040
#define RW_SLAB   (16*RW_STRIDE)
#define RA_BASE   (2*RW_SLAB)
#define RA_ST     16384
#define REC_SMEM  (RA_BASE + 3*RA_ST + 64)

__device__ __forceinline__ void gbar(unsigned* sp, unsigned goal)
{
    __syncthreads();
    __threadfence();
    if (threadIdx.x == 0) {
        atomicAdd(sp, 1u);
        unsigned v;
        do {
            asm volatile("ld.global.acquire.gpu.u32 %0, [%1];" : "=r"(v) : "l"(sp));
        } while (v < goal);
    }
    __syncthreads();
}

__device__ __forceinline__ float sig_f(float x)  { return 1.f/(1.f + __expf(-x)); }
__device__ __forceinline__ float tanh_f(float x) { return 2.f/(1.f + __expf(-2.f*x)) - 1.f; }

__device__ __forceinline__ void rec_issue(uint32_t sbase, uint32_t mb, int k,
                                          const __half* Ac)
{
    int slot = k % 3;
    uint32_t bar = mb + slot*8;
    BAR_EXPECT(bar, 16384u);
    BULK_CP(sbase + RA_BASE + slot*RA_ST, Ac + (long)k*Bdim*64, 16384u, bar);
}

__device__ __forceinline__ void rec_phase(uint32_t sbase, uint32_t wbase, uint32_t mb,
                                          const __half* __restrict__ Asrc,
                                          int tid, int wid, int lane,
                                          float acc[2][4],
                                          unsigned* ub, unsigned* ue, bool prime)
{
#pragma unroll
    for (int i = 0; i < 2; i++)
#pragma unroll
        for (int q = 0; q < 4; q++) acc[i][q] = 0.f;

    if (tid == 0) {
#pragma unroll
        for (int j = 0; j < 3; j++) {
            if (!prime) {
                MBARRIER_WAIT_PARITY(mb + 24 + j*8, ue[j] & 1);
                ue[j]++;
            }
            rec_issue(sbase, mb, j, Asrc);
        }
    }

    for (int k = 0; k < 8; k++) {
        int slot = k % 3;
        MBARRIER_WAIT_PARITY(mb + slot*8, ub[slot] & 1);
        ub[slot]++;

        uint32_t st = sbase + RA_BASE + slot*RA_ST;
#pragma unroll
        for (int ks = 0; ks < 4; ks++) {
            int krow = k*64 + ks*16 + ((lane >> 3) & 1)*8;
            uint32_t baddr = wbase + ((lane & 7) + ((lane >> 4) & 1)*8)*RW_STRIDE + krow*2;
            uint32_t rhi[4];
            ldm_x4(rhi, baddr);
            uint32_t bhi[2][2] = {{rhi[0], rhi[1]}, {rhi[2], rhi[3]}};
            uint32_t m = wid*16 + (lane & 15);
            uint32_t q = ks*2 + (lane >> 4);
            uint32_t ahi[4];
            ldm_x4(ahi, st + m*128 + (q ^ (m & 7))*16);
#pragma unroll
            for (int ni = 0; ni < 2; ni++)
                mma16816(acc[ni], ahi, bhi[ni]);
        }
        MBARRIER_ARRIVE(mb + 24 + slot*8);
        if (tid == 0 && k < 5) {
            MBARRIER_WAIT_PARITY(mb + 24 + slot*8, ue[slot] & 1);
            ue[slot]++;
            rec_issue(sbase, mb, k + 3, Asrc);
        }
    }
}

__global__ void __launch_bounds__(256, 1) rec_k(const float* __restrict__ Ua,
                                                const float* __restrict__ Uc,
                                                int t0, int t1, unsigned* syncp)
{
    extern __shared__ char smem[];
    const uint32_t sbase = smem_u32(smem);
    const uint32_t mb = sbase + RA_BASE + 3*RA_ST;
    const int tid = threadIdx.x, wid = tid >> 5, lane = tid & 31;
    const int bx = blockIdx.x;
    const int gg = bx >> 5;
    const int c0 = (bx & 31)*16;

    {
        const float* UaG = Ua + (long)gg*512*512;
        const float* UcG = Uc + (long)gg*512*512;
        for (int e = tid; e < 512*16; e += 256) {
            int k = e >> 4, j = e & 15;
            *(__half*)(smem + j*RW_STRIDE + k*2) =
                __float2half_rn(UaG[(long)k*512 + c0 + j]);
            *(__half*)(smem + RW_SLAB + j*RW_STRIDE + k*2) =
                __float2half_rn(UcG[(long)k*512 + c0 + j]);
        }
    }
    if (tid == 0) {
#pragma unroll
        for (int s = 0; s < 3; s++) {
            MBARRIER_INIT(mb + s*8, 1);
            MBARRIER_INIT(mb + 24 + s*8, 256);
        }
    }
    __syncthreads();

    unsigned goal = RC;
    unsigned ub[3] = {0u, 0u, 0u};
    unsigned ue[3] = {0u, 0u, 0u};
    bool prime = true;
    const long GS = (long)TBdim*Hdim;
    const long GH = (long)Bdim*Hdim;
    const __half* t6src = g_t6C + (long)gg*8*Bdim*64;

    const int ci = bx*512 + tid*2;
    float creg0 = g_c[ci], creg1 = g_c[ci + 1];

    for (int t = t0; t < t1; t++) {
        float acc[2][4];

        // phase A: t6[gg][:, c0..] = (h @ Ua[gg]) * t5 -> t6C hi
        rec_phase(sbase, sbase, mb, g_hC, tid, wid, lane, acc, ub, ue, prime);
        prime = false;
        {
            __half* Cz = g_t6C + (long)gg*8*Bdim*64;
            const float* t5g = g_t5 + (long)gg*GH;
#pragma unroll
            for (int ni = 0; ni < 2; ni++) {
                int col = c0 + ni*8 + (lane & 3)*2;
                int r0 = wid*16 + (lane >> 2), r1 = r0 + 8;
                int chunk = col >> 6, q = (col & 63) >> 3;
                float2 m0 = *(const float2*)(t5g + (long)r0*512 + col);
                float2 m1 = *(const float2*)(t5g + (long)r1*512 + col);
                __half2 h0 = __floats2half2_rn(acc[ni][0]*m0.x, acc[ni][1]*m0.y);
                __half2 h1 = __floats2half2_rn(acc[ni][2]*m1.x, acc[ni][3]*m1.y);
                *(__half2*)(Cz + ((long)chunk*Bdim + r0)*64 + (q ^ (r0 & 7))*8 + (col & 7)) = h0;
                *(__half2*)(Cz + ((long)chunk*Bdim + r1)*64 + (q ^ (r1 & 7))*8 + (col & 7)) = h1;
            }
        }
        gbar(syncp, goal); goal += RC;

        // phase B: gh[gg][:, c0..] = t6[gg] @ Uc[gg]
        rec_phase(sbase, sbase + RW_SLAB, mb, t6src, tid, wid, lane, acc, ub, ue, false);
        {
            float* Cz = g_gh + (long)gg*GH;
#pragma unroll
            for (int ni = 0; ni < 2; ni++) {
                int col = c0 + ni*8 + (lane & 3)*2;
                int r0 = wid*16 + (lane >> 2), r1 = r0 + 8;
                *(float2*)(Cz + (long)r0*512 + col) = make_float2(acc[ni][0], acc[ni][1]);
                *(float2*)(Cz + (long)r1*512 + col) = make_float2(acc[ni][2], acc[ni][3]);
            }
        }
        gbar(syncp, goal); goal += RC;

        // phase C: LSTM pointwise on batch row bx (c in registers)
        {
            const long so = (long)t*Bdim*Hdim;
            int i0 = bx*512 + tid*2;
            float hv[2];
#pragma unroll
            for (int u = 0; u < 2; u++) {
                int i = i0 + u;
                float pi = g_gx[0*GS + so + i] + g_gh[0*GH + i];
                float pf = g_gx[1*GS + so + i] + g_gh[1*GH + i];
                float po = g_gx[2*GS + so + i] + g_gh[2*GH + i];
                float pc = g_gx[3*GS + so + i] + g_gh[3*GH + i];
                float ig = sig_f(pi), fg = sig_f(pf), og = sig_f(po);
                float ct = tanh_f(pc);
                float cprev = u == 0 ? creg0 : creg1;
                float cn = fg*cprev + ig*ct;
                float hn = og*tanh_f(cn);
                if (u == 0) creg0 = cn; else creg1 = cn;
                hv[u] = hn;
            }
            __half2 hh = __floats2half2_rn(hv[0], hv[1]);
            int kcol = tid*2;
            int chunk = kcol >> 6, q = (kcol & 63) >> 3;
            *(__half2*)(g_hC + ((long)chunk*Bdim + bx)*64
                        + (q ^ (bx & 7))*8 + (kcol & 7)) = hh;
            int row = t*Bdim + bx;
            *(__half2*)(g_hsC + ((long)chunk*TBdim + row)*64
                        + (q ^ (row & 7))*8 + (kcol & 7)) = hh;
        }
        gbar(syncp, goal); goal += RC;
    }

    // persist cell state for the next half
    g_c[ci]     = creg0;
    g_c[ci + 1] = creg1;
}

// ---------------- launch ------------------------------------------------------
extern "C" void kernel_launch(void* const* d_in, const int* in_sizes, int n_in,
                              void* d_out, int out_size)
{
    const int*   caps = (const int*)  d_in[0];
    const float* tags = (const float*)d_in[1];
    const float* h0   = (const float*)d_in[2];
    const float* c0   = (const float*)d_in[3];
    const float* Wa   = (const float*)d_in[4];
    const float* Wb   = (const float*)d_in[5];
    const float* Wc   = (const float*)d_in[6];
    const float* Ua   = (const float*)d_in[7];
    const float* Ub   = (const float*)d_in[8];
    const float* Uc   = (const float*)d_in[9];
    const float* bi   = (const float*)d_in[10];
    const float* emb  = (const float*)d_in[11];
    const float* Wout = (const float*)d_in[12];
    const float* bout = (const float*)d_in[13];
    float* out = (float*)d_out;

    float *p_t2, *p_t5, *p_gx;
    unsigned *p_s1, *p_s2;
    __half *p_x2C, *p_t1C, *p_WaC, *p_WcC, *p_hsC, *p_WoC;
    cudaGetSymbolAddress((void**)&p_t2,  g_t2);
    cudaGetSymbolAddress((void**)&p_t5,  g_t5);
    cudaGetSymbolAddress((void**)&p_gx,  g_gx);
    cudaGetSymbolAddress((void**)&p_x2C, g_x2C);
    cudaGetSymbolAddress((void**)&p_t1C, g_t1C);
    cudaGetSymbolAddress((void**)&p_WaC, g_WaC);
    cudaGetSymbolAddress((void**)&p_WcC, g_WcC);
    cudaGetSymbolAddress((void**)&p_hsC, g_hsC);
    cudaGetSymbolAddress((void**)&p_WoC, g_WoC);
    cudaGetSymbolAddress((void**)&p_s1,  g_sync);
    cudaGetSymbolAddress((void**)&p_s2,  g_sync2);

    cudaFuncSetAttribute((const void*)mm_k<0>, cudaFuncAttributeMaxDynamicSharedMemorySize, MM_SMEM);
    cudaFuncSetAttribute((const void*)mm_k<1>, cudaFuncAttributeMaxDynamicSharedMemorySize, MM_SMEM);
    cudaFuncSetAttribute((const void*)mm_k<2>, cudaFuncAttributeMaxDynamicSharedMemorySize, MM_SMEM);
    cudaFuncSetAttribute((const void*)rec_k, cudaFuncAttributeMaxDynamicSharedMemorySize, REC_SMEM);

    static cudaEvent_t e1 = nullptr, e2 = nullptr;
    if (e1 == nullptr) {
        cudaEventCreateWithFlags(&e1, cudaEventDisableTiming);
        cudaEventCreateWithFlags(&e2, cudaEventDisableTiming);
    }

    k_gather<<<dim3(Bdim, Tdim), 128>>>(caps, emb);                          // 1
    k_convWC<<<dim3(16, 8, 8), 256>>>(Wa, Wc);                                // 2
    gemm_k<32,64,16,4,4><<<dim3(8,4,8), 128>>>(tags, Wb, Ub, p_t2, p_t5,      // 3
        Bdim, Rdim, NTG, (long)NTG*Rdim, (long)Bdim*Rdim);
    mm_k<1><<<dim3(24,4,4), 256, MM_SMEM>>>(p_x2C, p_WaC, nullptr,            // 4 (profiled)
        p_t1C, p_t2, 0L, 8L*512*64, 512, 0);
    k_init<<<256, 256>>>(h0, c0);                                             // 5
    k_convB<<<dim3(NPAD/128, 8), 256>>>(Wout);                                // 6
    mm_k<2><<<dim3(24,4,4), 256, MM_SMEM>>>(p_t1C, p_WcC, p_gx,               // 7
        nullptr, bi, 8L*TBdim*64, 8L*512*64, 512, 0);

    // recurrence first half
    rec_k<<<RC, 256, REC_SMEM>>>(Ua, Uc, 0, 12, p_s1);                        // 8

    // fork: out GEMM for timesteps [0,12) overlaps rec second half
    cudaEventRecord(e1, 0);
    cudaStreamWaitEvent(cudaStreamPerThread, e1, 0);
    mm_k<0><<<dim3(12, NPAD/128), 256, MM_SMEM, cudaStreamPerThread>>>(       // 9 (side)
        p_hsC, p_WoC, out, nullptr, bout, 0L, 0L, NPAD, 0);

    // recurrence second half (main stream, concurrent with #9)
    rec_k<<<RC, 256, REC_SMEM>>>(Ua, Uc, 12, 24, p_s2);                       // 10

    // out GEMM for timesteps [12,24)
    mm_k<0><<<dim3(12, NPAD/128), 256, MM_SMEM>>>(                            // 11
        p_hsC, p_WoC, out, nullptr, bout, 0L, 0L, NPAD, 12);

    // join side branch
    cudaEventRecord(e2, cudaStreamPerThread);
    cudaStreamWaitEvent(0, e2, 0);
}